// round 16
// baseline (speedup 1.0000x reference)
#include <cuda_runtime.h>
#include <math.h>
#include <stdint.h>

#define BB 16
#define SS 4096
#define HH 768
#define EE 8
#define CHUNKS 16
#define ROWS_PER_BLK 256
#define TS 8
#define NTILES 32          // ROWS_PER_BLK/TS
#define NBUF 3
#define NEB 4
#define TILE_BYTES (TS * HH * 4)   // 24576
#define XS_STRIDE 6144             // floats per x buffer

// smem layout in floats
#define XS_OFF    0                // 3 x 6144 = 18432
#define WLO_OFF   18432            // [768][4] = 3072  (e0..e3)
#define WHI_OFF   21504            // [768][4] = 3072  (e4..e7)
#define ASH_OFF   24576            // [8][256] = 2048
#define EXPPK_OFF 26624            // NEB x 64 u64 = 512 floats (8B aligned)
#define RED_OFF   27136            // [4 warps][32] = 128
#define BIAS_OFF  27264            // [8]
#define DENP_OFF  27272            // [64]
#define MBAR_OFF  27336            // 14 barriers x 8B = 28 floats (8B aligned)
#define SMEM_FLOATS 27368          // 109472 bytes -> 2 CTAs/SM (~213.8KB)

__device__ float g_num[(size_t)BB * CHUNKS * EE * HH];   // 6.3 MB
__device__ float g_den[BB * CHUNKS * EE];
__device__ float g_attn_scratch[(size_t)BB * EE * SS];

typedef unsigned long long u64;

__device__ __forceinline__ u64 pack2(float lo, float hi) {
    u64 r; asm("mov.b64 %0, {%1, %2};" : "=l"(r) : "f"(lo), "f"(hi)); return r;
}
__device__ __forceinline__ void unpack2(u64 v, float& lo, float& hi) {
    asm("mov.b64 {%0, %1}, %2;" : "=f"(lo), "=f"(hi) : "l"(v));
}
__device__ __forceinline__ void ffma2(u64& d, u64 a, u64 b) {
    asm("fma.rn.f32x2 %0, %1, %2, %3;" : "=l"(d) : "l"(a), "l"(b), "l"(d));
}
__device__ __forceinline__ void mbar_init(uint32_t mbar, uint32_t cnt) {
    asm volatile("mbarrier.init.shared.b64 [%0], %1;" :: "r"(mbar), "r"(cnt) : "memory");
}
__device__ __forceinline__ void mbar_expect_tx(uint32_t mbar, uint32_t bytes) {
    asm volatile("mbarrier.arrive.expect_tx.shared.b64 _, [%0], %1;"
                 :: "r"(mbar), "r"(bytes) : "memory");
}
__device__ __forceinline__ void mbar_arrive(uint32_t mbar) {
    asm volatile("mbarrier.arrive.shared.b64 _, [%0];" :: "r"(mbar) : "memory");
}
__device__ __forceinline__ void mbar_wait(uint32_t mbar, uint32_t parity) {
    asm volatile(
        "{\n\t.reg .pred P1;\n\t"
        "WAIT_%=:\n\t"
        "mbarrier.try_wait.parity.acquire.cta.shared::cta.b64 P1, [%0], %1, 0x989680;\n\t"
        "@P1 bra.uni DONE_%=;\n\t"
        "bra.uni WAIT_%=;\n\t"
        "DONE_%=:\n\t}"
        :: "r"(mbar), "r"(parity) : "memory");
}
__device__ __forceinline__ void bulk_g2s(uint32_t dst, const void* src,
                                         uint32_t bytes, uint32_t mbar) {
    asm volatile(
        "cp.async.bulk.shared::cluster.global.mbarrier::complete_tx::bytes "
        "[%0], [%1], %2, [%3];"
        :: "r"(dst), "l"(src), "r"(bytes), "r"(mbar) : "memory");
}
__device__ __forceinline__ uint32_t smem_u32(const void* p) {
    uint32_t a;
    asm("{ .reg .u64 t; cvta.to.shared.u64 t, %1; cvt.u32.u64 %0, t; }" : "=r"(a) : "l"(p));
    return a;
}

template <int HALF>
__device__ __forceinline__ void red_round(float* v, int lane) {
    bool hi = (lane & HALF) != 0;
#pragma unroll
    for (int m = 0; m < HALF; m++) {
        float mine  = hi ? v[m + HALF] : v[m];
        float yours = hi ? v[m]        : v[m + HALF];
        v[m] = mine + __shfl_xor_sync(0xffffffffu, yours, HALF);
    }
}

__global__ __launch_bounds__(256, 2)
void fused_attn_pass1(const float* __restrict__ x,
                      const float* __restrict__ W,
                      const float* __restrict__ bias,
                      float* __restrict__ attn_out)
{
    extern __shared__ float sm[];
    float* wlo     = sm + WLO_OFF;
    float* whi     = sm + WHI_OFF;
    float* a_sh    = sm + ASH_OFF;
    u64*   exp_pk  = (u64*)(sm + EXPPK_OFF);
    float* red_sh  = sm + RED_OFF;
    float* bias_sh = sm + BIAS_OFF;
    float* den_sh  = sm + DENP_OFF;

    const int t     = threadIdx.x;
    const int chunk = blockIdx.x;   // 0..15
    const int b     = blockIdx.y;   // 0..15
    const int lane  = t & 31;
    const int warp  = t >> 5;

    const uint32_t smem_base = smem_u32(sm);
    const uint32_t MB = smem_base + MBAR_OFF * 4u;
#define FULL_MB(i)     (MB + (i) * 8u)
#define EMPTY_MB(i)    (MB + 24u + (i) * 8u)
#define EXPFULL_MB(i)  (MB + 48u + (i) * 8u)
#define EXPEMPTY_MB(i) (MB + 80u + (i) * 8u)

    if (t == 0) {
#pragma unroll
        for (int i = 0; i < NBUF; i++) { mbar_init(FULL_MB(i), 1); mbar_init(EMPTY_MB(i), 256); }
#pragma unroll
        for (int i = 0; i < NEB; i++)  { mbar_init(EXPFULL_MB(i), 64); mbar_init(EXPEMPTY_MB(i), 128); }
    }
    // stage W transposed [h][e] split in two 4-wide halves, + bias
    for (int i = t; i < EE * HH; i += 256) {
        int e = i / HH, h = i % HH;
        float v = W[i];
        if (e < 4) wlo[h * 4 + e]       = v;
        else       whi[h * 4 + (e - 4)] = v;
    }
    if (t < EE) bias_sh[t] = bias[t];

    const float* xbase = x + ((size_t)b * SS + (size_t)chunk * ROWS_PER_BLK) * HH;
    __syncthreads();

    if (t == 128) {   // producer prologue: fill the 3-deep ring
#pragma unroll
        for (int k = 0; k < NBUF; k++) {
            mbar_expect_tx(FULL_MB(k), TILE_BYTES);
            bulk_g2s(smem_base + (XS_OFF + k * XS_STRIDE) * 4u,
                     xbase + (size_t)k * TS * HH, TILE_BYTES, FULL_MB(k));
        }
    }

    if (t < 128) {
        // ================= A-group: logits + softmax weights =================
        const int hg = t & 63;         // h-slice (64 wide, warp pair)
        const int sg = t >> 6;         // s-group: 4 rows each
        float den_part = 0.f;

        for (int tile = 0; tile < NTILES; tile++) {
            const int buf   = tile % NBUF;
            const int stage = tile & (NEB - 1);
            mbar_wait(FULL_MB(buf), (tile / NBUF) & 1);
            const float* xs = sm + XS_OFF + buf * XS_STRIDE;

            u64 acc2[4][4];
#pragma unroll
            for (int p = 0; p < 4; p++)
#pragma unroll
                for (int sl = 0; sl < 4; sl++) acc2[p][sl] = 0ull;

#pragma unroll
            for (int j = 0; j < 12; j++) {
                int h = hg + 64 * j;
                ulonglong2 wl = *(const ulonglong2*)&wlo[h << 2];
                ulonglong2 wh = *(const ulonglong2*)&whi[h << 2];
                u64 xp[4];
#pragma unroll
                for (int sl = 0; sl < 4; sl++) {
                    float xv = xs[(4 * sg + sl) * HH + h];
                    xp[sl] = pack2(xv, xv);
                }
#pragma unroll
                for (int sl = 0; sl < 4; sl++) {
                    ffma2(acc2[0][sl], wl.x, xp[sl]);
                    ffma2(acc2[1][sl], wl.y, xp[sl]);
                    ffma2(acc2[2][sl], wh.x, xp[sl]);
                    ffma2(acc2[3][sl], wh.y, xp[sl]);
                }
            }
            mbar_arrive(EMPTY_MB(buf));    // done reading xs

            float acc[32];
#pragma unroll
            for (int p = 0; p < 4; p++)
#pragma unroll
                for (int sl = 0; sl < 4; sl++)
                    unpack2(acc2[p][sl], acc[(2 * p) * 4 + sl], acc[(2 * p + 1) * 4 + sl]);

            red_round<16>(acc, lane);
            red_round<8>(acc, lane);
            red_round<4>(acc, lane);
            red_round<2>(acc, lane);
            red_round<1>(acc, lane);
            red_sh[warp * 32 + lane] = acc[0];   // warp-partial for m=lane
            asm volatile("bar.sync 1, 128;" ::: "memory");

            if (t < 64) {
                mbar_wait(EXPEMPTY_MB(stage), ((tile / NEB) ^ 1) & 1);
                int sgf = t >> 5;
                int m   = t & 31;
                int e   = m >> 2;
                int sl  = m & 3;
                float a = red_sh[(2 * sgf) * 32 + m] + red_sh[(2 * sgf + 1) * 32 + m]
                          + bias_sh[e];
                int s_local = 4 * sgf + sl;
                a_sh[e * ROWS_PER_BLK + tile * TS + s_local] = a;
                float ev = __expf(a);
                den_part += ev;
                exp_pk[stage * 64 + s_local * 8 + e] = pack2(ev, ev);
                mbar_arrive(EXPFULL_MB(stage));
            }
            asm volatile("bar.sync 1, 128;" ::: "memory");   // red_sh reuse next tile
        }
        if (t < 64) den_sh[t] = den_part;
    } else {
        // ================= B-group: weighted accumulation =================
        const int tb = t - 128;        // 0..127, owns h = 2*tb + 256k (+1)
        u64 accp[EE][3];
#pragma unroll
        for (int e = 0; e < EE; e++) { accp[e][0] = 0ull; accp[e][1] = 0ull; accp[e][2] = 0ull; }

        for (int tile = 0; tile < NTILES; tile++) {
            const int buf   = tile % NBUF;
            const int stage = tile & (NEB - 1);
            mbar_wait(EXPFULL_MB(stage), (tile / NEB) & 1);
            mbar_wait(FULL_MB(buf), (tile / NBUF) & 1);     // usually already passed
            const float* xs = sm + XS_OFF + buf * XS_STRIDE;
            const ulonglong2* eb = (const ulonglong2*)(exp_pk + stage * 64);

#pragma unroll
            for (int s = 0; s < TS; s++) {
                ulonglong2 q0 = eb[s * 4 + 0];   // (e0,e0),(e1,e1)
                ulonglong2 q1 = eb[s * 4 + 1];
                ulonglong2 q2 = eb[s * 4 + 2];
                ulonglong2 q3 = eb[s * 4 + 3];
                u64 x0 = *(const u64*)&xs[s * HH + 2 * tb];
                u64 x1 = *(const u64*)&xs[s * HH + 2 * tb + 256];
                u64 x2 = *(const u64*)&xs[s * HH + 2 * tb + 512];
                ffma2(accp[0][0], q0.x, x0); ffma2(accp[0][1], q0.x, x1); ffma2(accp[0][2], q0.x, x2);
                ffma2(accp[1][0], q0.y, x0); ffma2(accp[1][1], q0.y, x1); ffma2(accp[1][2], q0.y, x2);
                ffma2(accp[2][0], q1.x, x0); ffma2(accp[2][1], q1.x, x1); ffma2(accp[2][2], q1.x, x2);
                ffma2(accp[3][0], q1.y, x0); ffma2(accp[3][1], q1.y, x1); ffma2(accp[3][2], q1.y, x2);
                ffma2(accp[4][0], q2.x, x0); ffma2(accp[4][1], q2.x, x1); ffma2(accp[4][2], q2.x, x2);
                ffma2(accp[5][0], q2.y, x0); ffma2(accp[5][1], q2.y, x1); ffma2(accp[5][2], q2.y, x2);
                ffma2(accp[6][0], q3.x, x0); ffma2(accp[6][1], q3.x, x1); ffma2(accp[6][2], q3.x, x2);
                ffma2(accp[7][0], q3.y, x0); ffma2(accp[7][1], q3.y, x1); ffma2(accp[7][2], q3.y, x2);
            }
            mbar_arrive(EMPTY_MB(buf));
            mbar_arrive(EXPEMPTY_MB(stage));

            // producer: refill this buffer with tile+NBUF once fully released
            if (t == 128 && tile + NBUF < NTILES) {
                mbar_wait(EMPTY_MB(buf), (tile / NBUF) & 1);
                mbar_expect_tx(FULL_MB(buf), TILE_BYTES);
                bulk_g2s(smem_base + (XS_OFF + buf * XS_STRIDE) * 4u,
                         xbase + (size_t)(tile + NBUF) * TS * HH, TILE_BYTES, FULL_MB(buf));
            }
        }

        // write per-block numerator partials: h = 2*tb + 256k
        int blk = b * CHUNKS + chunk;
#pragma unroll
        for (int e = 0; e < EE; e++)
#pragma unroll
            for (int k = 0; k < 3; k++) {
                float lo, hi;
                unpack2(accp[e][k], lo, hi);
                float2 v = make_float2(lo, hi);
                *(float2*)&g_num[((size_t)blk * EE + e) * HH + 2 * tb + 256 * k] = v;
            }
    }

    __syncthreads();

    // atten logits: coalesced write from a_sh
    for (int f = t; f < EE * ROWS_PER_BLK; f += 256) {
        int e = f >> 8, i = f & 255;
        attn_out[((size_t)b * EE + e) * SS + chunk * ROWS_PER_BLK + i] = a_sh[f];
    }
    // denominator: 8 partials per e in den_sh
    if (t < EE) {
        float d = 0.f;
#pragma unroll
        for (int sgf = 0; sgf < 2; sgf++)
#pragma unroll
            for (int sl = 0; sl < 4; sl++)
                d += den_sh[sgf * 32 + t * 4 + sl];
        g_den[(b * CHUNKS + chunk) * EE + t] = d;
    }
}

// pass2: 2 blocks per (e,b), 384 threads = 96 h-quads x 4 chunk-groups.
// Each group sums 4 chunks; partials combine via smem; group 0 writes.
__global__ __launch_bounds__(384)
void fused_attn_pass2(float* __restrict__ out)
{
    __shared__ float4 part[4][96];
    __shared__ float inv_sh;

    const int e = blockIdx.y, b = blockIdx.z;
    const int hq  = (threadIdx.x % 96) + blockIdx.x * 96;   // h4 index 0..191
    const int grp = threadIdx.x / 96;                        // 0..3

    if (threadIdx.x == 0) {
        float den = 0.f;
#pragma unroll
        for (int c = 0; c < CHUNKS; c++) den += g_den[(b * CHUNKS + c) * EE + e];
        inv_sh = 1.0f / den;
    }

    const float4* base = (const float4*)(g_num + ((size_t)(b * CHUNKS + grp * 4) * EE + e) * HH) + hq;
    float4 s = make_float4(0.f, 0.f, 0.f, 0.f);
#pragma unroll
    for (int c = 0; c < 4; c++) {
        float4 v = base[(size_t)c * EE * HH / 4];
        s.x += v.x; s.y += v.y; s.z += v.z; s.w += v.w;
    }
    part[grp][threadIdx.x % 96] = s;
    __syncthreads();

    if (grp == 0) {
        int hl = threadIdx.x;     // 0..95
        float4 a = part[0][hl], b2 = part[1][hl], c2 = part[2][hl], d2 = part[3][hl];
        float inv = inv_sh;
        float4 r;
        r.x = (a.x + b2.x + c2.x + d2.x) * inv;
        r.y = (a.y + b2.y + c2.y + d2.y) * inv;
        r.z = (a.z + b2.z + c2.z + d2.z) * inv;
        r.w = (a.w + b2.w + c2.w + d2.w) * inv;
        ((float4*)(out + ((size_t)b * EE + e) * HH))[hq] = r;
    }
}

extern "C" void kernel_launch(void* const* d_in, const int* in_sizes, int n_in,
                              void* d_out, int out_size)
{
    const float* x    = (const float*)d_in[0];
    const float* W    = (const float*)d_in[1];
    const float* bias = (const float*)d_in[2];

    float* out_f = (float*)d_out;
    float* out_ptr;
    float* attn_ptr;

    const int OUT_N  = BB * EE * HH;          // 98304
    const int ATTN_N = BB * EE * SS;          // 524288

    if (out_size >= OUT_N + ATTN_N) {
        out_ptr  = out_f;
        attn_ptr = out_f + OUT_N;
    } else if (out_size == ATTN_N) {
        out_ptr  = nullptr;
        attn_ptr = out_f;
    } else {
        out_ptr  = out_f;
        float* dev_scratch;
        cudaGetSymbolAddress((void**)&dev_scratch, g_attn_scratch);
        attn_ptr = dev_scratch;
    }
    if (!out_ptr) {
        float* dev_scratch;
        cudaGetSymbolAddress((void**)&dev_scratch, g_attn_scratch);
        out_ptr = dev_scratch;
    }

    size_t smem_bytes = (size_t)SMEM_FLOATS * sizeof(float);
    cudaFuncSetAttribute(fused_attn_pass1,
                         cudaFuncAttributeMaxDynamicSharedMemorySize, (int)smem_bytes);

    fused_attn_pass1<<<dim3(CHUNKS, BB), 256, smem_bytes>>>(x, W, bias, attn_ptr);
    fused_attn_pass2<<<dim3(2, EE, BB), 384>>>(out_ptr);
}

// round 17
// speedup vs baseline: 1.0108x; 1.0108x over previous
#include <cuda_runtime.h>
#include <math.h>
#include <stdint.h>

#define BB 16
#define SS 4096
#define HH 768
#define EE 8
#define CHUNKS 37            // 36 x 112 rows + 1 x 64 rows = 4096
#define ROWS_BIG 112
#define TS 8
#define NT_BIG 14            // tiles in a 112-row chunk
#define NT_SMALL 8           // tiles in the 64-row tail chunk
#define NBUF 3
#define NEB 4
#define TILE_BYTES (TS * HH * 4)   // 24576
#define XS_STRIDE 6144             // floats per x buffer

// smem layout in floats
#define XS_OFF    0                // 3 x 6144 = 18432
#define WLO_OFF   18432            // [768][4] = 3072  (e0..e3)
#define WHI_OFF   21504            // [768][4] = 3072  (e4..e7)
#define ASH_OFF   24576            // [8][112] = 896
#define EXPPK_OFF 25472            // NEB x 64 u64 = 512 floats (8B aligned)
#define RED_OFF   25984            // [4 warps][32] = 128
#define BIAS_OFF  26112            // [8]
#define DENP_OFF  26120            // [64]
#define MBAR_OFF  26184            // 14 barriers x 8B = 28 floats (8B aligned)
#define SMEM_FLOATS 26216          // 104864 bytes -> 2 CTAs/SM

__device__ float g_num[(size_t)BB * CHUNKS * EE * HH];   // 13.9 MB
__device__ float g_den[BB * CHUNKS * EE];
__device__ float g_attn_scratch[(size_t)BB * EE * SS];

typedef unsigned long long u64;

__device__ __forceinline__ u64 pack2(float lo, float hi) {
    u64 r; asm("mov.b64 %0, {%1, %2};" : "=l"(r) : "f"(lo), "f"(hi)); return r;
}
__device__ __forceinline__ void unpack2(u64 v, float& lo, float& hi) {
    asm("mov.b64 {%0, %1}, %2;" : "=f"(lo), "=f"(hi) : "l"(v));
}
__device__ __forceinline__ void ffma2(u64& d, u64 a, u64 b) {
    asm("fma.rn.f32x2 %0, %1, %2, %3;" : "=l"(d) : "l"(a), "l"(b), "l"(d));
}
__device__ __forceinline__ void mbar_init(uint32_t mbar, uint32_t cnt) {
    asm volatile("mbarrier.init.shared.b64 [%0], %1;" :: "r"(mbar), "r"(cnt) : "memory");
}
__device__ __forceinline__ void mbar_expect_tx(uint32_t mbar, uint32_t bytes) {
    asm volatile("mbarrier.arrive.expect_tx.shared.b64 _, [%0], %1;"
                 :: "r"(mbar), "r"(bytes) : "memory");
}
__device__ __forceinline__ void mbar_arrive(uint32_t mbar) {
    asm volatile("mbarrier.arrive.shared.b64 _, [%0];" :: "r"(mbar) : "memory");
}
__device__ __forceinline__ void mbar_wait(uint32_t mbar, uint32_t parity) {
    asm volatile(
        "{\n\t.reg .pred P1;\n\t"
        "WAIT_%=:\n\t"
        "mbarrier.try_wait.parity.acquire.cta.shared::cta.b64 P1, [%0], %1, 0x989680;\n\t"
        "@P1 bra.uni DONE_%=;\n\t"
        "bra.uni WAIT_%=;\n\t"
        "DONE_%=:\n\t}"
        :: "r"(mbar), "r"(parity) : "memory");
}
__device__ __forceinline__ void bulk_g2s(uint32_t dst, const void* src,
                                         uint32_t bytes, uint32_t mbar) {
    asm volatile(
        "cp.async.bulk.shared::cluster.global.mbarrier::complete_tx::bytes "
        "[%0], [%1], %2, [%3];"
        :: "r"(dst), "l"(src), "r"(bytes), "r"(mbar) : "memory");
}
__device__ __forceinline__ uint32_t smem_u32(const void* p) {
    uint32_t a;
    asm("{ .reg .u64 t; cvta.to.shared.u64 t, %1; cvt.u32.u64 %0, t; }" : "=r"(a) : "l"(p));
    return a;
}

template <int HALF>
__device__ __forceinline__ void red_round(float* v, int lane) {
    bool hi = (lane & HALF) != 0;
#pragma unroll
    for (int m = 0; m < HALF; m++) {
        float mine  = hi ? v[m + HALF] : v[m];
        float yours = hi ? v[m]        : v[m + HALF];
        v[m] = mine + __shfl_xor_sync(0xffffffffu, yours, HALF);
    }
}

__global__ __launch_bounds__(256, 2)
void fused_attn_pass1(const float* __restrict__ x,
                      const float* __restrict__ W,
                      const float* __restrict__ bias,
                      float* __restrict__ attn_out)
{
    extern __shared__ float sm[];
    float* wlo     = sm + WLO_OFF;
    float* whi     = sm + WHI_OFF;
    float* a_sh    = sm + ASH_OFF;
    u64*   exp_pk  = (u64*)(sm + EXPPK_OFF);
    float* red_sh  = sm + RED_OFF;
    float* bias_sh = sm + BIAS_OFF;
    float* den_sh  = sm + DENP_OFF;

    const int t     = threadIdx.x;
    const int chunk = blockIdx.x;   // 0..36
    const int b     = blockIdx.y;   // 0..15
    const int lane  = t & 31;
    const int warp  = t >> 5;

    const int ntiles   = (chunk == CHUNKS - 1) ? NT_SMALL : NT_BIG;
    const int rows     = ntiles * TS;
    const int row_base = chunk * ROWS_BIG;

    const uint32_t smem_base = smem_u32(sm);
    const uint32_t MB = smem_base + MBAR_OFF * 4u;
#define FULL_MB(i)     (MB + (i) * 8u)
#define EMPTY_MB(i)    (MB + 24u + (i) * 8u)
#define EXPFULL_MB(i)  (MB + 48u + (i) * 8u)
#define EXPEMPTY_MB(i) (MB + 80u + (i) * 8u)

    if (t == 0) {
#pragma unroll
        for (int i = 0; i < NBUF; i++) { mbar_init(FULL_MB(i), 1); mbar_init(EMPTY_MB(i), 256); }
#pragma unroll
        for (int i = 0; i < NEB; i++)  { mbar_init(EXPFULL_MB(i), 64); mbar_init(EXPEMPTY_MB(i), 128); }
    }
    // stage W transposed [h][e] split in two 4-wide halves, + bias
    for (int i = t; i < EE * HH; i += 256) {
        int e = i / HH, h = i % HH;
        float v = W[i];
        if (e < 4) wlo[h * 4 + e]       = v;
        else       whi[h * 4 + (e - 4)] = v;
    }
    if (t < EE) bias_sh[t] = bias[t];

    const float* xbase = x + ((size_t)b * SS + (size_t)row_base) * HH;
    __syncthreads();

    if (t == 128) {   // producer prologue: fill the 3-deep ring
#pragma unroll
        for (int k = 0; k < NBUF; k++) {
            mbar_expect_tx(FULL_MB(k), TILE_BYTES);
            bulk_g2s(smem_base + (XS_OFF + k * XS_STRIDE) * 4u,
                     xbase + (size_t)k * TS * HH, TILE_BYTES, FULL_MB(k));
        }
    }

    if (t < 128) {
        // ================= A-group: logits + softmax weights =================
        const int hg = t & 63;         // h-slice (64 wide, warp pair)
        const int sg = t >> 6;         // s-group: 4 rows each
        float den_part = 0.f;

        for (int tile = 0; tile < ntiles; tile++) {
            const int buf   = tile % NBUF;
            const int stage = tile & (NEB - 1);
            mbar_wait(FULL_MB(buf), (tile / NBUF) & 1);
            const float* xs = sm + XS_OFF + buf * XS_STRIDE;

            u64 acc2[4][4];
#pragma unroll
            for (int p = 0; p < 4; p++)
#pragma unroll
                for (int sl = 0; sl < 4; sl++) acc2[p][sl] = 0ull;

#pragma unroll
            for (int j = 0; j < 12; j++) {
                int h = hg + 64 * j;
                ulonglong2 wl = *(const ulonglong2*)&wlo[h << 2];
                ulonglong2 wh = *(const ulonglong2*)&whi[h << 2];
                u64 xp[4];
#pragma unroll
                for (int sl = 0; sl < 4; sl++) {
                    float xv = xs[(4 * sg + sl) * HH + h];
                    xp[sl] = pack2(xv, xv);
                }
#pragma unroll
                for (int sl = 0; sl < 4; sl++) {
                    ffma2(acc2[0][sl], wl.x, xp[sl]);
                    ffma2(acc2[1][sl], wl.y, xp[sl]);
                    ffma2(acc2[2][sl], wh.x, xp[sl]);
                    ffma2(acc2[3][sl], wh.y, xp[sl]);
                }
            }
            mbar_arrive(EMPTY_MB(buf));    // done reading xs

            float acc[32];
#pragma unroll
            for (int p = 0; p < 4; p++)
#pragma unroll
                for (int sl = 0; sl < 4; sl++)
                    unpack2(acc2[p][sl], acc[(2 * p) * 4 + sl], acc[(2 * p + 1) * 4 + sl]);

            red_round<16>(acc, lane);
            red_round<8>(acc, lane);
            red_round<4>(acc, lane);
            red_round<2>(acc, lane);
            red_round<1>(acc, lane);
            red_sh[warp * 32 + lane] = acc[0];   // warp-partial for m=lane
            asm volatile("bar.sync 1, 128;" ::: "memory");

            if (t < 64) {
                mbar_wait(EXPEMPTY_MB(stage), ((tile / NEB) ^ 1) & 1);
                int sgf = t >> 5;
                int m   = t & 31;
                int e   = m >> 2;
                int sl  = m & 3;
                float a = red_sh[(2 * sgf) * 32 + m] + red_sh[(2 * sgf + 1) * 32 + m]
                          + bias_sh[e];
                int s_local = 4 * sgf + sl;
                a_sh[e * ROWS_BIG + tile * TS + s_local] = a;
                float ev = __expf(a);
                den_part += ev;
                exp_pk[stage * 64 + s_local * 8 + e] = pack2(ev, ev);
                mbar_arrive(EXPFULL_MB(stage));
            }
            asm volatile("bar.sync 1, 128;" ::: "memory");   // red_sh reuse next tile
        }
        if (t < 64) den_sh[t] = den_part;
    } else {
        // ================= B-group: weighted accumulation =================
        const int tb = t - 128;        // 0..127, owns h = 2*tb + 256k (+1)
        u64 accp[EE][3];
#pragma unroll
        for (int e = 0; e < EE; e++) { accp[e][0] = 0ull; accp[e][1] = 0ull; accp[e][2] = 0ull; }

        for (int tile = 0; tile < ntiles; tile++) {
            const int buf   = tile % NBUF;
            const int stage = tile & (NEB - 1);
            mbar_wait(EXPFULL_MB(stage), (tile / NEB) & 1);
            mbar_wait(FULL_MB(buf), (tile / NBUF) & 1);     // usually already passed
            const float* xs = sm + XS_OFF + buf * XS_STRIDE;
            const ulonglong2* eb = (const ulonglong2*)(exp_pk + stage * 64);

#pragma unroll
            for (int s = 0; s < TS; s++) {
                ulonglong2 q0 = eb[s * 4 + 0];   // (e0,e0),(e1,e1)
                ulonglong2 q1 = eb[s * 4 + 1];
                ulonglong2 q2 = eb[s * 4 + 2];
                ulonglong2 q3 = eb[s * 4 + 3];
                u64 x0 = *(const u64*)&xs[s * HH + 2 * tb];
                u64 x1 = *(const u64*)&xs[s * HH + 2 * tb + 256];
                u64 x2 = *(const u64*)&xs[s * HH + 2 * tb + 512];
                ffma2(accp[0][0], q0.x, x0); ffma2(accp[0][1], q0.x, x1); ffma2(accp[0][2], q0.x, x2);
                ffma2(accp[1][0], q0.y, x0); ffma2(accp[1][1], q0.y, x1); ffma2(accp[1][2], q0.y, x2);
                ffma2(accp[2][0], q1.x, x0); ffma2(accp[2][1], q1.x, x1); ffma2(accp[2][2], q1.x, x2);
                ffma2(accp[3][0], q1.y, x0); ffma2(accp[3][1], q1.y, x1); ffma2(accp[3][2], q1.y, x2);
                ffma2(accp[4][0], q2.x, x0); ffma2(accp[4][1], q2.x, x1); ffma2(accp[4][2], q2.x, x2);
                ffma2(accp[5][0], q2.y, x0); ffma2(accp[5][1], q2.y, x1); ffma2(accp[5][2], q2.y, x2);
                ffma2(accp[6][0], q3.x, x0); ffma2(accp[6][1], q3.x, x1); ffma2(accp[6][2], q3.x, x2);
                ffma2(accp[7][0], q3.y, x0); ffma2(accp[7][1], q3.y, x1); ffma2(accp[7][2], q3.y, x2);
            }
            mbar_arrive(EMPTY_MB(buf));
            mbar_arrive(EXPEMPTY_MB(stage));

            // producer: refill this buffer with tile+NBUF once fully released
            if (t == 128 && tile + NBUF < ntiles) {
                mbar_wait(EMPTY_MB(buf), (tile / NBUF) & 1);
                mbar_expect_tx(FULL_MB(buf), TILE_BYTES);
                bulk_g2s(smem_base + (XS_OFF + buf * XS_STRIDE) * 4u,
                         xbase + (size_t)(tile + NBUF) * TS * HH, TILE_BYTES, FULL_MB(buf));
            }
        }

        // write per-block numerator partials: h = 2*tb + 256k
        int blk = b * CHUNKS + chunk;
#pragma unroll
        for (int e = 0; e < EE; e++)
#pragma unroll
            for (int k = 0; k < 3; k++) {
                float lo, hi;
                unpack2(accp[e][k], lo, hi);
                float2 v = make_float2(lo, hi);
                *(float2*)&g_num[((size_t)blk * EE + e) * HH + 2 * tb + 256 * k] = v;
            }
    }

    __syncthreads();

    // atten logits: coalesced write from a_sh
    for (int f = t; f < EE * rows; f += 256) {
        int e = f / rows, i = f % rows;
        attn_out[((size_t)b * EE + e) * SS + row_base + i] = a_sh[e * ROWS_BIG + i];
    }
    // denominator: 8 partials per e in den_sh
    if (t < EE) {
        float d = 0.f;
#pragma unroll
        for (int sgf = 0; sgf < 2; sgf++)
#pragma unroll
            for (int sl = 0; sl < 4; sl++)
                d += den_sh[sgf * 32 + t * 4 + sl];
        g_den[(b * CHUNKS + chunk) * EE + t] = d;
    }
}

// pass2: 2 blocks per (e,b), 384 threads = 96 h-quads x 4 chunk-groups.
// Groups sum 9/9/9/10 chunks; partials combine via smem; group 0 writes.
__global__ __launch_bounds__(384)
void fused_attn_pass2(float* __restrict__ out)
{
    __shared__ float4 part[4][96];
    __shared__ float inv_sh;

    const int e = blockIdx.y, b = blockIdx.z;
    const int hq  = (threadIdx.x % 96) + blockIdx.x * 96;   // h4 index 0..191
    const int grp = threadIdx.x / 96;                        // 0..3

    if (threadIdx.x == 0) {
        float den = 0.f;
        for (int c = 0; c < CHUNKS; c++) den += g_den[(b * CHUNKS + c) * EE + e];
        inv_sh = 1.0f / den;
    }

    const int cstart = grp * 9;
    const int ccnt   = (grp == 3) ? 10 : 9;
    const float4* base = (const float4*)(g_num + ((size_t)(b * CHUNKS + cstart) * EE + e) * HH) + hq;
    float4 s = make_float4(0.f, 0.f, 0.f, 0.f);
#pragma unroll 10
    for (int c = 0; c < ccnt; c++) {
        float4 v = base[(size_t)c * EE * HH / 4];
        s.x += v.x; s.y += v.y; s.z += v.z; s.w += v.w;
    }
    part[grp][threadIdx.x % 96] = s;
    __syncthreads();

    if (grp == 0) {
        int hl = threadIdx.x;     // 0..95
        float4 a = part[0][hl], b2 = part[1][hl], c2 = part[2][hl], d2 = part[3][hl];
        float inv = inv_sh;
        float4 r;
        r.x = (a.x + b2.x + c2.x + d2.x) * inv;
        r.y = (a.y + b2.y + c2.y + d2.y) * inv;
        r.z = (a.z + b2.z + c2.z + d2.z) * inv;
        r.w = (a.w + b2.w + c2.w + d2.w) * inv;
        ((float4*)(out + ((size_t)b * EE + e) * HH))[hq] = r;
    }
}

extern "C" void kernel_launch(void* const* d_in, const int* in_sizes, int n_in,
                              void* d_out, int out_size)
{
    const float* x    = (const float*)d_in[0];
    const float* W    = (const float*)d_in[1];
    const float* bias = (const float*)d_in[2];

    float* out_f = (float*)d_out;
    float* out_ptr;
    float* attn_ptr;

    const int OUT_N  = BB * EE * HH;          // 98304
    const int ATTN_N = BB * EE * SS;          // 524288

    if (out_size >= OUT_N + ATTN_N) {
        out_ptr  = out_f;
        attn_ptr = out_f + OUT_N;
    } else if (out_size == ATTN_N) {
        out_ptr  = nullptr;
        attn_ptr = out_f;
    } else {
        out_ptr  = out_f;
        float* dev_scratch;
        cudaGetSymbolAddress((void**)&dev_scratch, g_attn_scratch);
        attn_ptr = dev_scratch;
    }
    if (!out_ptr) {
        float* dev_scratch;
        cudaGetSymbolAddress((void**)&dev_scratch, g_attn_scratch);
        out_ptr = dev_scratch;
    }

    size_t smem_bytes = (size_t)SMEM_FLOATS * sizeof(float);
    cudaFuncSetAttribute(fused_attn_pass1,
                         cudaFuncAttributeMaxDynamicSharedMemorySize, (int)smem_bytes);

    fused_attn_pass1<<<dim3(CHUNKS, BB), 256, smem_bytes>>>(x, W, bias, attn_ptr);
    fused_attn_pass2<<<dim3(2, EE, BB), 384>>>(out_ptr);
}